// round 4
// baseline (speedup 1.0000x reference)
#include <cuda_runtime.h>
#include <cstdint>

#define BB   8
#define SS   128
#define DD   300
#define EE   50
#define DEPC 50
#define RROWS 8
#define NTHR 608

// ---------------- scratch (static device globals; no allocation) ----------------
__device__ float g_Pa[BB * SS * DEPC];   // node @ Wa^T
__device__ float g_Pb[BB * SS * DEPC];   // node @ Wb^T

using ull = unsigned long long;

// ---------------- f32x2 packed-math helpers ----------------
__device__ __forceinline__ ull pk2(float x, float y) {
    ull r; asm("mov.b64 %0, {%1,%2};" : "=l"(r) : "f"(x), "f"(y)); return r;
}
__device__ __forceinline__ ull f2fma(ull a, ull b, ull c) {
    ull d; asm("fma.rn.f32x2 %0, %1, %2, %3;" : "=l"(d) : "l"(a), "l"(b), "l"(c)); return d;
}
__device__ __forceinline__ ull f2add(ull a, ull b) {
    ull d; asm("add.rn.f32x2 %0, %1, %2;" : "=l"(d) : "l"(a), "l"(b)); return d;
}
__device__ __forceinline__ void upk2(ull v, float& x, float& y) {
    asm("mov.b64 {%0,%1}, %2;" : "=f"(x), "=f"(y) : "l"(v));
}

// ---------------- smem layout (floats) ----------------
#define OFF_MSP   0        // 1024  packed M row-pairs  [t*4+rp] -> f2 (rows 2rp,2rp+1)
#define OFF_M0    1024     // 1024  partial M (half 0)
#define OFF_M1    2048     // 1024  partial M (half 1)
#define OFF_AX    3072     // 3000  Ax f2 [d*5+rp]
#define OFF_NS    6072     // 3000  node f2 [d*5+rp]
#define OFF_H     9072     // 4800  scratch: AxH / GH / Pp (disjoint windows)
#define OFF_RED   13872    // 152   (19 warps x 8)
#define OFF_MEAN  14024    // 8
#define OFF_INVD  14032    // 8
#define SMEM_FLOATS 14040
#define SMEM_BYTES  (SMEM_FLOATS * 4)

#define MSU(t, rp) (*reinterpret_cast<const ull*>(&MsP[(t) * 4 + (rp)]))
#define AXU(d, rp) (*reinterpret_cast<const ull*>(&AxP[(d) * 5 + (rp)]))
#define NSU(d, rp) (*reinterpret_cast<const ull*>(&NsP[(d) * 5 + (rp)]))

__global__ __launch_bounds__(NTHR, 1) void k_fused(
    const float* __restrict__ wps, const float* __restrict__ sl,
    const float* __restrict__ x,   const float* __restrict__ Ww,
    const float* __restrict__ Wb,  const float* __restrict__ lna,
    const float* __restrict__ lnb, const float* __restrict__ W1w,
    float* __restrict__ node_out)
{
    extern __shared__ float sm[];
    float*  MsPf  = sm + OFF_MSP;
    float2* MsP   = reinterpret_cast<float2*>(MsPf);
    float*  M0    = sm + OFF_M0;
    float*  M1    = sm + OFF_M1;
    float2* AxP   = reinterpret_cast<float2*>(sm + OFF_AX);
    float2* NsP   = reinterpret_cast<float2*>(sm + OFF_NS);
    float*  Hf    = sm + OFF_H;
    float*  red   = sm + OFF_RED;
    float*  means = sm + OFF_MEAN;
    float*  invd  = sm + OFF_INVD;

    const int tid = threadIdx.x;
    const int b   = blockIdx.x >> 4;
    const int s0  = (blockIdx.x & 15) * RROWS;

    // ================= Phase 0: M rows (52 MB stream), split 2 ways =================
    // tasks 0..1023  : wps floats [0,24)  + sl e [0,25)   -> M0[entry]
    // tasks 1024..2047: wps floats [24,50) + sl e [25,50)  -> M1[entry]
    for (int k = tid; k < 2048; k += NTHR) {
        int eh = k >> 10, entry = k & 1023;
        int r = entry >> 7, t = entry & 127;
        const float* wrow = wps + ((size_t)((b * SS + s0 + r) * SS) + t) * EE;
        const float* sp   = sl + (size_t)b * EE * SS * SS + (s0 + r) * SS + t;
        float s = 0.f;
        if (eh == 0) {
            const float2* w2 = reinterpret_cast<const float2*>(wrow);
#pragma unroll
            for (int i = 0; i < 12; i++) { float2 v = w2[i]; s += v.x + v.y; }
#pragma unroll
            for (int e = 0; e < 25; e++) s += sp[e * SS * SS];
            M0[entry] = s;
        } else {
            const float2* w2 = reinterpret_cast<const float2*>(wrow + 24);
#pragma unroll
            for (int i = 0; i < 13; i++) { float2 v = w2[i]; s += v.x + v.y; }
#pragma unroll
            for (int e = 25; e < 50; e++) s += sp[e * SS * SS];
            M1[entry] = s;
        }
    }
    __syncthreads();
    for (int i = tid; i < 1024; i += NTHR) {
        int r = i >> 7, t = i & 127;
        MsPf[(t * 4 + (r >> 1)) * 2 + (r & 1)] = (M0[i] + M1[i]) * (1.0f / EE);
    }
    __syncthreads();

    // ================= Phase 1: Ax[r][d] = sum_t M[r][t]*X[t][d], t split 2 ways ====
    ull axacc[4] = {0, 0, 0, 0};
    if (tid < 600) {
        int th = (tid >= 300);
        int d  = tid - 300 * th;
        const float* xb = x + (size_t)b * SS * DD + d;
        int t0 = th * 64;
#pragma unroll 4
        for (int t = t0; t < t0 + 64; t++) {
            float xv = xb[t * DD];
            ull x2 = pk2(xv, xv);
#pragma unroll
            for (int rp = 0; rp < 4; rp++) axacc[rp] = f2fma(MSU(t, rp), x2, axacc[rp]);
        }
        if (th) {
            ull* H = reinterpret_cast<ull*>(Hf);
#pragma unroll
            for (int rp = 0; rp < 4; rp++) H[d * 4 + rp] = axacc[rp];
        }
    }
    __syncthreads();
    if (tid < 300) {
        ull* H = reinterpret_cast<ull*>(Hf);
#pragma unroll
        for (int rp = 0; rp < 4; rp++)
            *reinterpret_cast<ull*>(&AxP[tid * 5 + rp]) = f2add(axacc[rp], H[tid * 4 + rp]);
    }
    __syncthreads();

    // ================= Phase 2: g = Ax @ W^T + b  (j-pairs x d-halves) ==============
    // tid<300: jp = tid>>1 owns columns j0=2jp, j1=2jp+1; dh = tid&1 owns d-half.
    ull a0[4] = {0, 0, 0, 0}, a1[4] = {0, 0, 0, 0};
    int jp = tid >> 1, dh = tid & 1;
    int j0 = jp * 2, j1 = j0 + 1;
    if (tid < 300) {
        const float2* w0 = reinterpret_cast<const float2*>(Ww + (size_t)j0 * DD + dh * 150);
        const float2* w1 = reinterpret_cast<const float2*>(Ww + (size_t)j1 * DD + dh * 150);
        int dbase = dh * 150;
#pragma unroll 5
        for (int i = 0; i < 75; i++) {
            float2 wa = w0[i], wb = w1[i];
            int d = dbase + 2 * i;
            ull wax = pk2(wa.x, wa.x), wbx = pk2(wb.x, wb.x);
#pragma unroll
            for (int rp = 0; rp < 4; rp++) {
                ull ax = AXU(d, rp);
                a0[rp] = f2fma(wax, ax, a0[rp]);
                a1[rp] = f2fma(wbx, ax, a1[rp]);
            }
            ull way = pk2(wa.y, wa.y), wby = pk2(wb.y, wb.y);
#pragma unroll
            for (int rp = 0; rp < 4; rp++) {
                ull ax = AXU(d + 1, rp);
                a0[rp] = f2fma(way, ax, a0[rp]);
                a1[rp] = f2fma(wby, ax, a1[rp]);
            }
        }
    }
    // combine d-halves: odd tids publish, even tids own full g for (j0, j1)
    if (tid < 300 && dh) {
        ull* GH = reinterpret_cast<ull*>(Hf);
#pragma unroll
        for (int rp = 0; rp < 4; rp++) { GH[jp * 8 + rp] = a0[rp]; GH[jp * 8 + 4 + rp] = a1[rp]; }
    }
    __syncthreads();

    float gj0[RROWS], gj1[RROWS];
    const bool owner = (tid < 300) && (dh == 0);
    if (owner) {
        ull* GH = reinterpret_cast<ull*>(Hf);
        float bj0 = Wb[j0], bj1 = Wb[j1];
#pragma unroll
        for (int rp = 0; rp < 4; rp++) {
            ull f0 = f2add(a0[rp], GH[jp * 8 + rp]);
            ull f1 = f2add(a1[rp], GH[jp * 8 + 4 + rp]);
            upk2(f0, gj0[2 * rp], gj0[2 * rp + 1]);
            upk2(f1, gj1[2 * rp], gj1[2 * rp + 1]);
        }
#pragma unroll
        for (int r = 0; r < RROWS; r++) { gj0[r] += bj0; gj1[r] += bj1; }
    }

    // ================= Phase 3: LayerNorm (ddof=1) + relu ===========================
    const int lane = tid & 31, warp = tid >> 5;
    {
        float s[RROWS];
#pragma unroll
        for (int r = 0; r < RROWS; r++) s[r] = owner ? (gj0[r] + gj1[r]) : 0.f;
#pragma unroll
        for (int off = 16; off; off >>= 1)
#pragma unroll
            for (int r = 0; r < RROWS; r++) s[r] += __shfl_down_sync(0xffffffffu, s[r], off);
        if (lane == 0)
#pragma unroll
            for (int r = 0; r < RROWS; r++) red[warp * RROWS + r] = s[r];
    }
    __syncthreads();
    if (tid < RROWS) {
        float s = 0.f;
#pragma unroll
        for (int w = 0; w < NTHR / 32; w++) s += red[w * RROWS + tid];
        means[tid] = s * (1.0f / DD);
    }
    __syncthreads();
    {
        float s[RROWS];
#pragma unroll
        for (int r = 0; r < RROWS; r++) {
            float d0 = owner ? (gj0[r] - means[r]) : 0.f;
            float d1 = owner ? (gj1[r] - means[r]) : 0.f;
            s[r] = d0 * d0 + d1 * d1;
        }
#pragma unroll
        for (int off = 16; off; off >>= 1)
#pragma unroll
            for (int r = 0; r < RROWS; r++) s[r] += __shfl_down_sync(0xffffffffu, s[r], off);
        if (lane == 0)
#pragma unroll
            for (int r = 0; r < RROWS; r++) red[warp * RROWS + r] = s[r];
    }
    __syncthreads();
    if (tid < RROWS) {
        float s = 0.f;
#pragma unroll
        for (int w = 0; w < NTHR / 32; w++) s += red[w * RROWS + tid];
        float stdv = sqrtf(s * (1.0f / (DD - 1)));   // ddof = 1
        invd[tid] = 1.0f / (stdv + 1e-6f);
    }
    __syncthreads();

    if (owner) {
        float la0 = lna[j0], la1 = lna[j1], lb0 = lnb[j0], lb1 = lnb[j1];
        float n0[RROWS], n1[RROWS];
#pragma unroll
        for (int r = 0; r < RROWS; r++) {
            float v0 = la0 * (gj0[r] - means[r]) * invd[r] + lb0;
            float v1 = la1 * (gj1[r] - means[r]) * invd[r] + lb1;
            n0[r] = v0 > 0.f ? v0 : 0.f;
            n1[r] = v1 > 0.f ? v1 : 0.f;
            *reinterpret_cast<float2*>(node_out + (size_t)(b * SS + s0 + r) * DD + j0) =
                make_float2(n0[r], n1[r]);
        }
#pragma unroll
        for (int rp = 0; rp < 4; rp++) {
            NsP[j0 * 5 + rp] = make_float2(n0[2 * rp], n0[2 * rp + 1]);
            NsP[j1 * 5 + rp] = make_float2(n1[2 * rp], n1[2 * rp + 1]);
        }
    }
    __syncthreads();

    // ================= Phase 4: pa/pb, 6-way d-split over 600 threads ==============
    float2* Pp = reinterpret_cast<float2*>(Hf);   // 600*4 f2 = 4800 f
    if (tid < 600) {
        int o = tid / 6, seg = tid - 6 * o;       // o in [0,100): e=o%50, half=o/50
        int e = o % DEPC, half = o / DEPC;
        const float2* w2 = reinterpret_cast<const float2*>(
            W1w + (size_t)e * (2 * DD) + half * DD + seg * 50);
        ull acc[4] = {0, 0, 0, 0};
        int dbase = seg * 50;
#pragma unroll 5
        for (int i = 0; i < 25; i++) {
            float2 wv = w2[i];
            int d = dbase + 2 * i;
            ull wx = pk2(wv.x, wv.x);
#pragma unroll
            for (int rp = 0; rp < 4; rp++) acc[rp] = f2fma(wx, NSU(d, rp), acc[rp]);
            ull wy = pk2(wv.y, wv.y);
#pragma unroll
            for (int rp = 0; rp < 4; rp++) acc[rp] = f2fma(wy, NSU(d + 1, rp), acc[rp]);
        }
#pragma unroll
        for (int rp = 0; rp < 4; rp++)
            Pp[(o * 6 + seg) * 4 + rp] = *reinterpret_cast<float2*>(&acc[rp]);
    }
    __syncthreads();

    if (tid < 400) {
        int o = tid >> 2, rp = tid & 3;
        int e = o % DEPC, half = o / DEPC;
        float sx = 0.f, sy = 0.f;
#pragma unroll
        for (int s = 0; s < 6; s++) {
            float2 p = Pp[(o * 6 + s) * 4 + rp];
            sx += p.x; sy += p.y;
        }
        float* dst = (half == 0 ? g_Pa : g_Pb) + (size_t)(b * SS + s0) * DEPC + e;
        dst[(2 * rp)     * DEPC] = sx;
        dst[(2 * rp + 1) * DEPC] = sy;
    }
}

// =======================================================================
// k_edge: edge[b,i,j,e] = pa[b,j,e] + pb[b,i,e] + W1_b[e]
// 400 threads = 16 j-slots x 25 e-pairs: e2 is loop-invariant -> pb+bias in ONE
// register; body = LDG.64 + add.f32x2 + STG.64, exactly 8 iterations.
// =======================================================================
__global__ __launch_bounds__(400) void k_edge(const float* __restrict__ W1b,
                                              float* __restrict__ edge) {
    const int bi  = blockIdx.x;        // b*S + i
    const int b   = bi >> 7;
    const int tid = threadIdx.x;
    const int e2  = tid % 25;          // which float2 of the 50-float e-dim
    const int j0  = tid / 25;          // starting j slot

    float2 w  = reinterpret_cast<const float2*>(W1b)[e2];
    float2 pv = reinterpret_cast<const float2*>(g_Pb + (size_t)bi * DEPC)[e2];
    ull pr = pk2(pv.x + w.x, pv.y + w.y);

    const ull* pa  = reinterpret_cast<const ull*>(g_Pa + (size_t)b * SS * DEPC);
    ull*       out = reinterpret_cast<ull*>(edge + (size_t)bi * SS * DEPC);
#pragma unroll
    for (int j = j0; j < SS; j += 16) {
        int idx = j * 25 + e2;
        out[idx] = f2add(pa[idx], pr);
    }
}

// =======================================================================
extern "C" void kernel_launch(void* const* d_in, const int* in_sizes, int n_in,
                              void* d_out, int out_size) {
    const float* wps = (const float*)d_in[0];
    /* d_in[1] = weight_adj (int64) — unused */
    const float* x   = (const float*)d_in[2];
    const float* sl  = (const float*)d_in[3];
    const float* Ww  = (const float*)d_in[4];
    const float* Wb  = (const float*)d_in[5];
    const float* lna = (const float*)d_in[6];
    const float* lnb = (const float*)d_in[7];
    const float* W1w = (const float*)d_in[8];
    const float* W1b = (const float*)d_in[9];

    float* out  = (float*)d_out;
    float* node = out;                       // B*S*D floats
    float* edge = out + BB * SS * DD;        // B*S*S*DEP floats

    cudaFuncSetAttribute((const void*)k_fused,
                         cudaFuncAttributeMaxDynamicSharedMemorySize, SMEM_BYTES);

    k_fused<<<BB * (SS / RROWS), NTHR, SMEM_BYTES>>>(wps, sl, x, Ww, Wb, lna, lnb, W1w, node);
    k_edge<<<BB * SS, 400>>>(W1b, edge);
}